// round 2
// baseline (speedup 1.0000x reference)
#include <cuda_runtime.h>

// ---------------- scratch (no allocations allowed) ----------------
__device__ float g_WqEff[512 * 512];
__device__ float g_WkEff[512 * 512];
__device__ float g_biasQ[512];
__device__ float g_biasK[512];
__device__ float g_qh[1024 * 512];     // [b,t, h*64+e]
__device__ float g_khb[1024 * 512];    // [b,s, h*64+e]  (includes b_h)
__device__ float g_Kp[1024 * 512];     // [b,s, h*64+d]
__device__ float g_score[16 * 512 * 512]; // [b*8+h, t, s]
__device__ float g_merged[1024 * 512]; // [b,t, h*64+d]

__device__ __forceinline__ float tanh_fast(float x) {
    float y;
    asm("tanh.approx.f32 %0, %1;" : "=f"(y) : "f"(x));
    return y;
}

// ---------------- tiny bias-prep: bias = b @ Wh (+ b_h on key side) ----------------
__global__ void __launch_bounds__(256) prep_bias_kernel(
    const float* __restrict__ bq, const float* __restrict__ Wq_h,
    const float* __restrict__ bk, const float* __restrict__ Wk_h,
    const float* __restrict__ b_h) {
    int i = blockIdx.x * 256 + threadIdx.x;
    if (i >= 1024) return;
    int side = i >> 9, col = i & 511;
    int h = col >> 6, e = col & 63;
    const float* bb = side ? bk : bq;
    const float* Wh = (side ? Wk_h : Wq_h) + h * 4096;
    float s = 0.f;
#pragma unroll 8
    for (int d = 0; d < 64; d++) s += bb[h * 64 + d] * Wh[d * 64 + e];
    if (side) g_biasK[col] = s + b_h[col];
    else      g_biasQ[col] = s;
}

// ---------------- generic batched FFMA GEMM: C = A@B (+bias) ----------------
// 64x64 tile, BK=16, 256 threads, 4x4 per thread. Requires M%64==0, N%64==0, K%16==0.
__global__ void __launch_bounds__(256) gemm64(
    const float* __restrict__ A, int lda, long aOut, long aIn,
    const float* __restrict__ B, int ldb, long bOut, long bIn,
    const float* __restrict__ bias,
    float* __restrict__ C, int ldc, long cOut, long cIn,
    int M, int N, int K, int batchInner) {
    int z = blockIdx.z;
    int zo = z / batchInner, zi = z - zo * batchInner;
    A += zo * aOut + zi * aIn;
    B += zo * bOut + zi * bIn;
    C += zo * cOut + zi * cIn;

    const int m0 = blockIdx.y * 64, n0 = blockIdx.x * 64;
    __shared__ float As[16][64];
    __shared__ float Bs[16][64];
    int tid = threadIdx.x;
    int tx = tid & 15, ty = tid >> 4;
    int aRow = tid >> 2, aCol4 = (tid & 3) << 2;   // A tile 64x16
    int bRow = tid >> 4, bCol4 = (tid & 15) << 2;  // B tile 16x64

    float acc[4][4] = {};
    for (int k0 = 0; k0 < K; k0 += 16) {
        float4 av = *(const float4*)&A[(long)(m0 + aRow) * lda + k0 + aCol4];
        float4 bv = *(const float4*)&B[(long)(k0 + bRow) * ldb + n0 + bCol4];
        __syncthreads();
        As[aCol4 + 0][aRow] = av.x;
        As[aCol4 + 1][aRow] = av.y;
        As[aCol4 + 2][aRow] = av.z;
        As[aCol4 + 3][aRow] = av.w;
        *(float4*)&Bs[bRow][bCol4] = bv;
        __syncthreads();
#pragma unroll
        for (int k = 0; k < 16; k++) {
            float a[4], b[4];
            *(float4*)a = *(const float4*)&As[k][ty * 4];
            *(float4*)b = *(const float4*)&Bs[k][tx * 4];
#pragma unroll
            for (int i = 0; i < 4; i++)
#pragma unroll
                for (int j = 0; j < 4; j++) acc[i][j] += a[i] * b[j];
        }
    }
    float b4[4] = {0.f, 0.f, 0.f, 0.f};
    if (bias) *(float4*)b4 = *(const float4*)&bias[n0 + tx * 4];
#pragma unroll
    for (int i = 0; i < 4; i++) {
        float4 o = make_float4(acc[i][0] + b4[0], acc[i][1] + b4[1],
                               acc[i][2] + b4[2], acc[i][3] + b4[3]);
        *(float4*)&C[(long)(m0 + ty * 4 + i) * ldc + n0 + tx * 4] = o;
    }
}

// ---------------- Bahdanau score kernel (MUFU-bound) ----------------
// score[z,t,s] = sum_e va[h,e] * tanh(qh[t,e] + khb[s,e]) ; z = b*8+h
__global__ void __launch_bounds__(256) score_kernel(
    const float* __restrict__ qh, const float* __restrict__ khb,
    const float* __restrict__ va, float* __restrict__ score) {
    const int z = blockIdx.z;
    const int b = z >> 3, h = z & 7;
    const int t0 = blockIdx.y * 64, s0 = blockIdx.x * 64;

    __shared__ float qs[64][68];
    __shared__ float ks[64][68];
    __shared__ float vsh[64];

    const int tid = threadIdx.x;
#pragma unroll
    for (int r = 0; r < 4; r++) {
        int idx = tid + r * 256;
        int row = idx >> 4;
        int c4 = (idx & 15) << 2;
        float4 qv = *(const float4*)&qh[(long)((b * 512 + t0 + row) * 512) + h * 64 + c4];
        *(float4*)&qs[row][c4] = qv;
        float4 kv = *(const float4*)&khb[(long)((b * 512 + s0 + row) * 512) + h * 64 + c4];
        *(float4*)&ks[row][c4] = kv;
    }
    if (tid < 64) vsh[tid] = va[h * 64 + tid];
    __syncthreads();

    const int tm = (tid >> 4) * 4, tn = (tid & 15) * 4;
    float acc[4][4] = {};
#pragma unroll 4
    for (int e = 0; e < 64; e += 4) {
        float v4[4], q[4][4], kk[4][4];
        *(float4*)v4 = *(const float4*)&vsh[e];
#pragma unroll
        for (int i = 0; i < 4; i++) *(float4*)q[i] = *(const float4*)&qs[tm + i][e];
#pragma unroll
        for (int j = 0; j < 4; j++) *(float4*)kk[j] = *(const float4*)&ks[tn + j][e];
#pragma unroll
        for (int i = 0; i < 4; i++)
#pragma unroll
            for (int j = 0; j < 4; j++) {
                acc[i][j] += v4[0] * tanh_fast(q[i][0] + kk[j][0]);
                acc[i][j] += v4[1] * tanh_fast(q[i][1] + kk[j][1]);
                acc[i][j] += v4[2] * tanh_fast(q[i][2] + kk[j][2]);
                acc[i][j] += v4[3] * tanh_fast(q[i][3] + kk[j][3]);
            }
    }
#pragma unroll
    for (int i = 0; i < 4; i++) {
        float4 o = make_float4(acc[i][0], acc[i][1], acc[i][2], acc[i][3]);
        *(float4*)&score[(long)((z * 512 + t0 + tm + i) * 512) + s0 + tn] = o;
    }
}

// ---------------- softmax over s (one warp per row of 512) ----------------
__global__ void __launch_bounds__(256) softmax_kernel(float* __restrict__ score) {
    int warp = threadIdx.x >> 5, lane = threadIdx.x & 31;
    long row = (long)blockIdx.x * 8 + warp;  // 8192 rows
    float* p = score + row * 512;
    float v[16];
    float m = -1e30f;
#pragma unroll
    for (int i = 0; i < 16; i++) { v[i] = p[lane + i * 32]; m = fmaxf(m, v[i]); }
#pragma unroll
    for (int o = 16; o; o >>= 1) m = fmaxf(m, __shfl_xor_sync(0xffffffffu, m, o));
    float s = 0.f;
#pragma unroll
    for (int i = 0; i < 16; i++) { v[i] = __expf(v[i] - m); s += v[i]; }
#pragma unroll
    for (int o = 16; o; o >>= 1) s += __shfl_xor_sync(0xffffffffu, s, o);
    float inv = __fdividef(1.f, s);
#pragma unroll
    for (int i = 0; i < 16; i++) p[lane + i * 32] = v[i] * inv;
}

// ---------------- launcher ----------------
extern "C" void kernel_launch(void* const* d_in, const int* in_sizes, int n_in,
                              void* d_out, int out_size) {
    const float* query = (const float*)d_in[0];
    const float* key   = (const float*)d_in[1];
    // d_in[2] = value : unused by the reference computation
    const float* Wq   = (const float*)d_in[3];
    const float* bq   = (const float*)d_in[4];
    const float* Wk   = (const float*)d_in[5];
    const float* bk   = (const float*)d_in[6];
    // d_in[7] = Wv, d_in[8] = bv : unused
    const float* Wq_h = (const float*)d_in[9];
    const float* Wk_h = (const float*)d_in[10];
    const float* va_h = (const float*)d_in[11];
    const float* b_h  = (const float*)d_in[12];
    const float* Wo   = (const float*)d_in[13];
    const float* bo   = (const float*)d_in[14];
    float* out = (float*)d_out;

    float *pWqEff, *pWkEff, *pBiasQ, *pBiasK, *pQh, *pKhb, *pKp, *pScore, *pMerged;
    cudaGetSymbolAddress((void**)&pWqEff, g_WqEff);
    cudaGetSymbolAddress((void**)&pWkEff, g_WkEff);
    cudaGetSymbolAddress((void**)&pBiasQ, g_biasQ);
    cudaGetSymbolAddress((void**)&pBiasK, g_biasK);
    cudaGetSymbolAddress((void**)&pQh, g_qh);
    cudaGetSymbolAddress((void**)&pKhb, g_khb);
    cudaGetSymbolAddress((void**)&pKp, g_Kp);
    cudaGetSymbolAddress((void**)&pScore, g_score);
    cudaGetSymbolAddress((void**)&pMerged, g_merged);

    // 1) fold per-head maps into effective weights + biases
    prep_bias_kernel<<<4, 256>>>(bq, Wq_h, bk, Wk_h, b_h);
    // Wq_eff[:, h*64+e] = Wq[:, h*64+d] @ Wq_h[h]   (batched over h)
    gemm64<<<dim3(1, 8, 8), 256>>>(Wq, 512, 0, 64, Wq_h, 64, 0, 4096, nullptr,
                                   pWqEff, 512, 0, 64, 512, 64, 64, 8);
    gemm64<<<dim3(1, 8, 8), 256>>>(Wk, 512, 0, 64, Wk_h, 64, 0, 4096, nullptr,
                                   pWkEff, 512, 0, 64, 512, 64, 64, 8);

    // 2) projections: qh = query@WqEff + biasQ ; khb = key@WkEff + biasK ; Kp = key@Wk + bk
    gemm64<<<dim3(8, 16, 1), 256>>>(query, 512, 0, 0, pWqEff, 512, 0, 0, pBiasQ,
                                    pQh, 512, 0, 0, 1024, 512, 512, 1);
    gemm64<<<dim3(8, 16, 1), 256>>>(key, 512, 0, 0, pWkEff, 512, 0, 0, pBiasK,
                                    pKhb, 512, 0, 0, 1024, 512, 512, 1);
    gemm64<<<dim3(8, 16, 1), 256>>>(key, 512, 0, 0, Wk, 512, 0, 0, bk,
                                    pKp, 512, 0, 0, 1024, 512, 512, 1);

    // 3) additive scores (MUFU-bound)
    score_kernel<<<dim3(8, 8, 16), 256>>>(pQh, pKhb, va_h, pScore);

    // 4) softmax over s
    softmax_kernel<<<1024, 256>>>(pScore);

    // 5) heads = attn @ K  -> merged [b,t,h*64+d]   (batched over b,h)
    gemm64<<<dim3(1, 8, 16), 256>>>(pScore, 512, 2097152L, 262144L,
                                    pKp, 512, 262144L, 64L, nullptr,
                                    pMerged, 512, 262144L, 64L, 512, 64, 512, 8);

    // 6) out = merged @ Wo + bo
    gemm64<<<dim3(8, 16, 1), 256>>>(pMerged, 512, 0, 0, Wo, 512, 0, 0, bo,
                                    out, 512, 0, 0, 1024, 512, 512, 1);
}

// round 5
// speedup vs baseline: 1.3177x; 1.3177x over previous
#include <cuda_runtime.h>
#include <cstdint>

// ---------------- scratch (no allocations allowed) ----------------
__device__ float g_WqEffT[512 * 512];   // [n=h*64+e][k=din]
__device__ float g_WkEffT[512 * 512];
__device__ float g_WkT[512 * 512];      // [n][k]
__device__ float g_WoT[512 * 512];
__device__ float g_biasQ[512];
__device__ float g_biasK[512];
__device__ float g_qh[1024 * 512];      // [b,t, h*64+e]
__device__ float g_khb[1024 * 512];     // [b,s, h*64+e]
__device__ float g_KpT[16 * 64 * 512];  // [(b*8+h)][d][s]
__device__ float g_score[16 * 512 * 512];
__device__ float g_merged[1024 * 512];

__device__ __forceinline__ uint32_t f2tf32(float x) {
    uint32_t u;
    asm("cvt.rna.tf32.f32 %0, %1;" : "=r"(u) : "f"(x));
    return u;
}
__device__ __forceinline__ float tanh_fast(float x) {
    float y;
    asm("tanh.approx.f32 %0, %1;" : "=f"(y) : "f"(x));
    return y;
}
__device__ __forceinline__ void mma_m16n8k8(float* d, const uint32_t* a,
                                            const uint32_t* b) {
    asm volatile(
        "mma.sync.aligned.m16n8k8.row.col.f32.tf32.tf32.f32 "
        "{%0,%1,%2,%3}, {%4,%5,%6,%7}, {%8,%9}, {%0,%1,%2,%3};"
        : "+f"(d[0]), "+f"(d[1]), "+f"(d[2]), "+f"(d[3])
        : "r"(a[0]), "r"(a[1]), "r"(a[2]), "r"(a[3]), "r"(b[0]), "r"(b[1]));
}

// ---------------- bias prep ----------------
__global__ void __launch_bounds__(256) prep_bias_kernel(
    const float* __restrict__ bq, const float* __restrict__ Wq_h,
    const float* __restrict__ bk, const float* __restrict__ Wk_h,
    const float* __restrict__ b_h) {
    int i = blockIdx.x * 256 + threadIdx.x;
    if (i >= 1024) return;
    int side = i >> 9, col = i & 511;
    int h = col >> 6, e = col & 63;
    const float* bb = side ? bk : bq;
    const float* Wh = (side ? Wk_h : Wq_h) + h * 4096;
    float s = 0.f;
#pragma unroll 8
    for (int d = 0; d < 64; d++) s += bb[h * 64 + d] * Wh[d * 64 + e];
    if (side) g_biasK[col] = s + b_h[col];
    else      g_biasQ[col] = s;
}

// ---------------- small FFMA GEMM (prep only), optional transposed store ----
__global__ void __launch_bounds__(256) gemm64(
    const float* __restrict__ A, int lda, long aOut, long aIn,
    const float* __restrict__ B, int ldb, long bOut, long bIn,
    const float* __restrict__ bias,
    float* __restrict__ C, int ldc, long cOut, long cIn,
    int M, int N, int K, int batchInner, int transC) {
    int z = blockIdx.z;
    int zo = z / batchInner, zi = z - zo * batchInner;
    A += zo * aOut + zi * aIn;
    B += zo * bOut + zi * bIn;
    C += zo * cOut + zi * cIn;

    const int m0 = blockIdx.y * 64, n0 = blockIdx.x * 64;
    __shared__ float As[16][64];
    __shared__ float Bs[16][64];
    int tid = threadIdx.x;
    int tx = tid & 15, ty = tid >> 4;
    int aRow = tid >> 2, aCol4 = (tid & 3) << 2;
    int bRow = tid >> 4, bCol4 = (tid & 15) << 2;

    float acc[4][4] = {};
    for (int k0 = 0; k0 < K; k0 += 16) {
        float4 av = *(const float4*)&A[(long)(m0 + aRow) * lda + k0 + aCol4];
        float4 bv = *(const float4*)&B[(long)(k0 + bRow) * ldb + n0 + bCol4];
        __syncthreads();
        As[aCol4 + 0][aRow] = av.x;
        As[aCol4 + 1][aRow] = av.y;
        As[aCol4 + 2][aRow] = av.z;
        As[aCol4 + 3][aRow] = av.w;
        *(float4*)&Bs[bRow][bCol4] = bv;
        __syncthreads();
#pragma unroll
        for (int k = 0; k < 16; k++) {
            float a[4], b[4];
            *(float4*)a = *(const float4*)&As[k][ty * 4];
            *(float4*)b = *(const float4*)&Bs[k][tx * 4];
#pragma unroll
            for (int i = 0; i < 4; i++)
#pragma unroll
                for (int j = 0; j < 4; j++) acc[i][j] += a[i] * b[j];
        }
    }
    float b4[4] = {0.f, 0.f, 0.f, 0.f};
    if (bias) *(float4*)b4 = *(const float4*)&bias[n0 + tx * 4];
    if (!transC) {
#pragma unroll
        for (int i = 0; i < 4; i++) {
            float4 o = make_float4(acc[i][0] + b4[0], acc[i][1] + b4[1],
                                   acc[i][2] + b4[2], acc[i][3] + b4[3]);
            *(float4*)&C[(long)(m0 + ty * 4 + i) * ldc + n0 + tx * 4] = o;
        }
    } else {
#pragma unroll
        for (int i = 0; i < 4; i++)
#pragma unroll
            for (int j = 0; j < 4; j++)
                C[(long)(n0 + tx * 4 + j) * ldc + m0 + ty * 4 + i] = acc[i][j] + b4[j];
    }
}

// ---------------- 512x512 transpose (for Wk, Wo) ----------------
__global__ void __launch_bounds__(256) transpose512(
    const float* __restrict__ Wk, const float* __restrict__ Wo,
    float* __restrict__ WkT, float* __restrict__ WoT) {
    const float* S = blockIdx.z ? Wo : Wk;
    float* D = blockIdx.z ? WoT : WkT;
    __shared__ float t[32][33];
    int x = blockIdx.x * 32 + threadIdx.x;
    int y0 = blockIdx.y * 32;
#pragma unroll
    for (int r = threadIdx.y; r < 32; r += 8) t[r][threadIdx.x] = S[(long)(y0 + r) * 512 + x];
    __syncthreads();
    int xo = y0 + threadIdx.x;
#pragma unroll
    for (int r = threadIdx.y; r < 32; r += 8)
        D[(long)(blockIdx.x * 32 + r) * 512 + xo] = t[threadIdx.x][r];
}

// ---------------- tf32 mma.sync GEMM ----------------
// C[m,n] = sum_k A[m,k] * B[n,k]   (B pre-transposed, K-major)
// CTA tile 64x64, K-chunk 32, 8 warps in 2x4 (warp tile 32x16 = 2x2 mma tiles).
// Smem in fragment-major layout: A frag = 1 LDS.128 / B frag = 1 LDS.64.
// mode 0: row-major C (+bias). mode 1: KpT scatter C[((b*8+h)*64+d)*512+s] (+bias).
__global__ void __launch_bounds__(256) gemm_mma(
    const float* __restrict__ A, int lda, long aOut, long aIn,
    const float* __restrict__ B, int ldb, long bOut, long bIn,
    const float* __restrict__ bias,
    float* __restrict__ C, int ldc, long cOut, long cIn,
    int K, int batchInner, int mode) {
    __shared__ uint32_t As[2][2048];  // [mt(4)][ks(4)][lane(32)][reg(4)]
    __shared__ uint32_t Bs[2][2048];  // [nt(8)][ks(4)][lane(32)][reg(2)]

    const int tid = threadIdx.x;
    const int wid = tid >> 5, lane = tid & 31;
    int z = blockIdx.z;
    int zo = z / batchInner, zi = z - zo * batchInner;
    A += zo * aOut + zi * aIn;
    B += zo * bOut + zi * bIn;
    C += zo * cOut + zi * cIn;
    const int m0 = blockIdx.y * 64, n0 = blockIdx.x * 64;

    const int nch = K >> 5;
    float4 apf[2], bpf[2];

    auto ldg = [&](int ch) {
        int k0 = ch << 5;
#pragma unroll
        for (int r = 0; r < 2; r++) {
            int j = tid + 256 * r;
            int row = j >> 3, c4 = (j & 7) << 2;
            apf[r] = *(const float4*)&A[(long)(m0 + row) * lda + k0 + c4];
            bpf[r] = *(const float4*)&B[(long)(n0 + row) * ldb + k0 + c4];
        }
    };
    auto sts = [&](int buf) {
#pragma unroll
        for (int r = 0; r < 2; r++) {
            int j = tid + 256 * r;
            int row = j >> 3, c4 = (j & 7) << 2;
            int ks = c4 >> 3, chi = (c4 >> 2) & 1;
            // A: mma tile row-block of 16
            {
                int mt = row >> 4, rlo = row & 15;
                int reg = (rlo >> 3) + (chi << 1);
                int off = (mt * 4 + ks) * 128 + (rlo & 7) * 16 + reg;
                As[buf][off +  0] = f2tf32(apf[r].x);
                As[buf][off +  4] = f2tf32(apf[r].y);
                As[buf][off +  8] = f2tf32(apf[r].z);
                As[buf][off + 12] = f2tf32(apf[r].w);
            }
            // B: mma tile col-block of 8
            {
                int nt = row >> 3, g = row & 7;
                int off = (nt * 4 + ks) * 64 + g * 8 + chi;
                Bs[buf][off + 0] = f2tf32(bpf[r].x);
                Bs[buf][off + 2] = f2tf32(bpf[r].y);
                Bs[buf][off + 4] = f2tf32(bpf[r].z);
                Bs[buf][off + 6] = f2tf32(bpf[r].w);
            }
        }
    };

    const int wm = wid >> 2, wn = wid & 3;
    float acc[2][2][4] = {};

    auto compute = [&](int buf) {
#pragma unroll
        for (int ks = 0; ks < 4; ks++) {
            uint32_t a[2][4], b[2][2];
#pragma unroll
            for (int i = 0; i < 2; i++) {
                int mt = wm * 2 + i;
                uint4 v = *(const uint4*)&As[buf][(mt * 4 + ks) * 128 + lane * 4];
                a[i][0] = v.x; a[i][1] = v.y; a[i][2] = v.z; a[i][3] = v.w;
            }
#pragma unroll
            for (int j = 0; j < 2; j++) {
                int nt = wn * 2 + j;
                uint2 v = *(const uint2*)&Bs[buf][(nt * 4 + ks) * 64 + lane * 2];
                b[j][0] = v.x; b[j][1] = v.y;
            }
#pragma unroll
            for (int i = 0; i < 2; i++)
#pragma unroll
                for (int j = 0; j < 2; j++) mma_m16n8k8(acc[i][j], a[i], b[j]);
        }
    };

    ldg(0);
    sts(0);
    __syncthreads();
    for (int ch = 0; ch < nch; ch++) {
        if (ch + 1 < nch) ldg(ch + 1);
        compute(ch & 1);
        if (ch + 1 < nch) sts((ch + 1) & 1);
        __syncthreads();
    }

    const int g = lane >> 2, t = lane & 3;
#pragma unroll
    for (int i = 0; i < 2; i++)
#pragma unroll
        for (int j = 0; j < 2; j++) {
            int m = m0 + wm * 32 + i * 16 + g;
            int n = n0 + wn * 16 + j * 8 + t * 2;
            float c0 = acc[i][j][0], c1 = acc[i][j][1];
            float c2 = acc[i][j][2], c3 = acc[i][j][3];
            if (bias) {
                float b0 = bias[n], b1 = bias[n + 1];
                c0 += b0; c1 += b1; c2 += b0; c3 += b1;
            }
            if (mode == 0) {
                *(float2*)&C[(long)m * ldc + n] = make_float2(c0, c1);
                *(float2*)&C[(long)(m + 8) * ldc + n] = make_float2(c2, c3);
            } else {
                int b0i = m >> 9, s = m & 511;
                int b1i = (m + 8) >> 9, s1 = (m + 8) & 511;
                long r0 = (long)(((b0i << 3) + (n >> 6)) * 64 + (n & 63)) * 512;
                long r0b = (long)(((b0i << 3) + ((n + 1) >> 6)) * 64 + ((n + 1) & 63)) * 512;
                long r1 = (long)(((b1i << 3) + (n >> 6)) * 64 + (n & 63)) * 512;
                long r1b = (long)(((b1i << 3) + ((n + 1) >> 6)) * 64 + ((n + 1) & 63)) * 512;
                C[r0 + s] = c0;
                C[r0b + s] = c1;
                C[r1 + s1] = c2;
                C[r1b + s1] = c3;
            }
        }
}

// ---------------- Bahdanau score kernel (MUFU-bound) ----------------
__global__ void __launch_bounds__(256) score_kernel(
    const float* __restrict__ qh, const float* __restrict__ khb,
    const float* __restrict__ va, float* __restrict__ score) {
    const int z = blockIdx.z;
    const int b = z >> 3, h = z & 7;
    const int t0 = blockIdx.y * 64, s0 = blockIdx.x * 64;

    __shared__ float qs[64][68];
    __shared__ float ks[64][68];
    __shared__ float vsh[64];

    const int tid = threadIdx.x;
#pragma unroll
    for (int r = 0; r < 4; r++) {
        int idx = tid + r * 256;
        int row = idx >> 4;
        int c4 = (idx & 15) << 2;
        float4 qv = *(const float4*)&qh[(long)((b * 512 + t0 + row) * 512) + h * 64 + c4];
        *(float4*)&qs[row][c4] = qv;
        float4 kv = *(const float4*)&khb[(long)((b * 512 + s0 + row) * 512) + h * 64 + c4];
        *(float4*)&ks[row][c4] = kv;
    }
    if (tid < 64) vsh[tid] = va[h * 64 + tid];
    __syncthreads();

    const int tm = (tid >> 4) * 4, tn = (tid & 15) * 4;
    float acc[4][4] = {};
#pragma unroll 4
    for (int e = 0; e < 64; e += 4) {
        float v4[4], q[4][4], kk[4][4];
        *(float4*)v4 = *(const float4*)&vsh[e];
#pragma unroll
        for (int i = 0; i < 4; i++) *(float4*)q[i] = *(const float4*)&qs[tm + i][e];
#pragma unroll
        for (int j = 0; j < 4; j++) *(float4*)kk[j] = *(const float4*)&ks[tn + j][e];
#pragma unroll
        for (int i = 0; i < 4; i++)
#pragma unroll
            for (int j = 0; j < 4; j++) {
                acc[i][j] += v4[0] * tanh_fast(q[i][0] + kk[j][0]);
                acc[i][j] += v4[1] * tanh_fast(q[i][1] + kk[j][1]);
                acc[i][j] += v4[2] * tanh_fast(q[i][2] + kk[j][2]);
                acc[i][j] += v4[3] * tanh_fast(q[i][3] + kk[j][3]);
            }
    }
#pragma unroll
    for (int i = 0; i < 4; i++) {
        float4 o = make_float4(acc[i][0], acc[i][1], acc[i][2], acc[i][3]);
        *(float4*)&score[(long)((z * 512 + t0 + tm + i) * 512) + s0 + tn] = o;
    }
}

// ---------------- softmax over s ----------------
__global__ void __launch_bounds__(256) softmax_kernel(float* __restrict__ score) {
    int warp = threadIdx.x >> 5, lane = threadIdx.x & 31;
    long row = (long)blockIdx.x * 8 + warp;
    float* p = score + row * 512;
    float v[16];
    float m = -1e30f;
#pragma unroll
    for (int i = 0; i < 16; i++) { v[i] = p[lane + i * 32]; m = fmaxf(m, v[i]); }
#pragma unroll
    for (int o = 16; o; o >>= 1) m = fmaxf(m, __shfl_xor_sync(0xffffffffu, m, o));
    float s = 0.f;
#pragma unroll
    for (int i = 0; i < 16; i++) { v[i] = __expf(v[i] - m); s += v[i]; }
#pragma unroll
    for (int o = 16; o; o >>= 1) s += __shfl_xor_sync(0xffffffffu, s, o);
    float inv = __fdividef(1.f, s);
#pragma unroll
    for (int i = 0; i < 16; i++) p[lane + i * 32] = v[i] * inv;
}

// ---------------- launcher ----------------
extern "C" void kernel_launch(void* const* d_in, const int* in_sizes, int n_in,
                              void* d_out, int out_size) {
    const float* query = (const float*)d_in[0];
    const float* key   = (const float*)d_in[1];
    const float* Wq   = (const float*)d_in[3];
    const float* bq   = (const float*)d_in[4];
    const float* Wk   = (const float*)d_in[5];
    const float* bk   = (const float*)d_in[6];
    const float* Wq_h = (const float*)d_in[9];
    const float* Wk_h = (const float*)d_in[10];
    const float* va_h = (const float*)d_in[11];
    const float* b_h  = (const float*)d_in[12];
    const float* Wo   = (const float*)d_in[13];
    const float* bo   = (const float*)d_in[14];
    float* out = (float*)d_out;

    float *pWqEffT, *pWkEffT, *pWkT, *pWoT, *pBiasQ, *pBiasK;
    float *pQh, *pKhb, *pKpT, *pScore, *pMerged;
    cudaGetSymbolAddress((void**)&pWqEffT, g_WqEffT);
    cudaGetSymbolAddress((void**)&pWkEffT, g_WkEffT);
    cudaGetSymbolAddress((void**)&pWkT, g_WkT);
    cudaGetSymbolAddress((void**)&pWoT, g_WoT);
    cudaGetSymbolAddress((void**)&pBiasQ, g_biasQ);
    cudaGetSymbolAddress((void**)&pBiasK, g_biasK);
    cudaGetSymbolAddress((void**)&pQh, g_qh);
    cudaGetSymbolAddress((void**)&pKhb, g_khb);
    cudaGetSymbolAddress((void**)&pKpT, g_KpT);
    cudaGetSymbolAddress((void**)&pScore, g_score);
    cudaGetSymbolAddress((void**)&pMerged, g_merged);

    // 1) fold per-head maps -> transposed effective weights + biases
    prep_bias_kernel<<<4, 256>>>(bq, Wq_h, bk, Wk_h, b_h);
    gemm64<<<dim3(1, 8, 8), 256>>>(Wq, 512, 0, 64, Wq_h, 64, 0, 4096, nullptr,
                                   pWqEffT, 512, 0, 64L * 512, 512, 64, 64, 8, 1);
    gemm64<<<dim3(1, 8, 8), 256>>>(Wk, 512, 0, 64, Wk_h, 64, 0, 4096, nullptr,
                                   pWkEffT, 512, 0, 64L * 512, 512, 64, 64, 8, 1);
    transpose512<<<dim3(16, 16, 2), dim3(32, 8)>>>(Wk, Wo, pWkT, pWoT);

    // 2) projections via tf32 mma.sync
    gemm_mma<<<dim3(8, 16, 1), 256>>>(query, 512, 0, 0, pWqEffT, 512, 0, 0, pBiasQ,
                                      pQh, 512, 0, 0, 512, 1, 0);
    gemm_mma<<<dim3(8, 16, 1), 256>>>(key, 512, 0, 0, pWkEffT, 512, 0, 0, pBiasK,
                                      pKhb, 512, 0, 0, 512, 1, 0);
    gemm_mma<<<dim3(8, 16, 1), 256>>>(key, 512, 0, 0, pWkT, 512, 0, 0, bk,
                                      pKpT, 512, 0, 0, 512, 1, 1);  // KpT scatter

    // 3) additive scores + softmax
    score_kernel<<<dim3(8, 8, 16), 256>>>(pQh, pKhb, va_h, pScore);
    softmax_kernel<<<1024, 256>>>(pScore);

    // 4) heads = attn @ K  (batched over b,h; B = KpT K-major)
    gemm_mma<<<dim3(1, 8, 16), 256>>>(pScore, 512, 2097152L, 262144L,
                                      pKpT, 512, 262144L, 32768L, nullptr,
                                      pMerged, 512, 262144L, 64L, 512, 8, 0);

    // 5) out = merged @ Wo + bo
    gemm_mma<<<dim3(8, 16, 1), 256>>>(pMerged, 512, 0, 0, pWoT, 512, 0, 0, bo,
                                      out, 512, 0, 0, 512, 1, 0);
}

// round 7
// speedup vs baseline: 1.4672x; 1.1135x over previous
#include <cuda_runtime.h>
#include <cstdint>

// ---------------- scratch (no allocations allowed) ----------------
__device__ float g_WqEffT[512 * 512];   // [n=h*64+e][k]
__device__ float g_WkEffT[512 * 512];
__device__ float g_WkT[512 * 512];
__device__ float g_WoT[512 * 512];
__device__ float g_biasQ[512];
__device__ float g_biasK[512];
__device__ float g_qhE[16 * 64 * 512];   // [z][e][t]
__device__ float g_khbE[16 * 64 * 512];  // [z][e][s]
__device__ float g_KpR[16 * 512 * 64];   // [z][s][d]
__device__ float g_merged[1024 * 512];   // [b*512+t][h*64+d]

__device__ __forceinline__ uint32_t f2tf32(float x) {
    uint32_t u;
    asm("cvt.rna.tf32.f32 %0, %1;" : "=r"(u) : "f"(x));
    return u;
}
__device__ __forceinline__ float tanh_fast(float x) {
    float y;
    asm("tanh.approx.f32 %0, %1;" : "=f"(y) : "f"(x));
    return y;
}
__device__ __forceinline__ void mma_m16n8k8(float* d, const uint32_t* a,
                                            const uint32_t* b) {
    asm volatile(
        "mma.sync.aligned.m16n8k8.row.col.f32.tf32.tf32.f32 "
        "{%0,%1,%2,%3}, {%4,%5,%6,%7}, {%8,%9}, {%0,%1,%2,%3};"
        : "+f"(d[0]), "+f"(d[1]), "+f"(d[2]), "+f"(d[3])
        : "r"(a[0]), "r"(a[1]), "r"(a[2]), "r"(a[3]), "r"(b[0]), "r"(b[1]));
}

// ==================== merged prep kernel ====================
// blocks [0,4): bias fold; [4,132): eff-weight folds; [132,644): transposes
__global__ void __launch_bounds__(256) prep_all(
    const float* __restrict__ bq, const float* __restrict__ Wq_h,
    const float* __restrict__ bk, const float* __restrict__ Wk_h,
    const float* __restrict__ b_h, const float* __restrict__ Wq,
    const float* __restrict__ Wk, const float* __restrict__ Wo) {
    __shared__ float sm[2][64][68];
    const int bx = blockIdx.x, tid = threadIdx.x;
    if (bx < 4) {
        int i = bx * 256 + tid;
        int side = i >> 9, col = i & 511, h = col >> 6, e = col & 63;
        const float* bb = side ? bk : bq;
        const float* Wh = (side ? Wk_h : Wq_h) + h * 4096;
        float s = 0.f;
#pragma unroll 8
        for (int d = 0; d < 64; d++) s += bb[h * 64 + d] * Wh[d * 64 + e];
        if (side) g_biasK[col] = s + b_h[col];
        else      g_biasQ[col] = s;
    } else if (bx < 132) {
        int q = bx - 4;
        int side = q >> 6;
        q &= 63;
        int h = q >> 3, k0 = (q & 7) * 64;
        const float* W = side ? Wk : Wq;
        const float* Wh = (side ? Wk_h : Wq_h) + h * 4096;
        float* C = (side ? g_WkEffT : g_WqEffT) + h * 64 * 512;
#pragma unroll
        for (int r = 0; r < 4; r++) {
            int idx = tid + r * 256;
            int row = idx >> 4, c4 = (idx & 15) << 2;
            *(float4*)&sm[0][row][c4] = *(const float4*)&W[(long)(k0 + row) * 512 + h * 64 + c4];
            *(float4*)&sm[1][row][c4] = *(const float4*)&Wh[row * 64 + c4];
        }
        __syncthreads();
        const int tmm = (tid >> 4) * 4, tnn = (tid & 15) * 4;
        float acc[4][4] = {};
#pragma unroll 8
        for (int d = 0; d < 64; d++) {
            float a[4], b[4];
#pragma unroll
            for (int i = 0; i < 4; i++) a[i] = sm[0][tmm + i][d];
            *(float4*)b = *(const float4*)&sm[1][d][tnn];
#pragma unroll
            for (int i = 0; i < 4; i++)
#pragma unroll
                for (int j = 0; j < 4; j++) acc[i][j] += a[i] * b[j];
        }
#pragma unroll
        for (int i = 0; i < 4; i++)
#pragma unroll
            for (int j = 0; j < 4; j++)
                C[(long)(tnn + j) * 512 + k0 + tmm + i] = acc[i][j];
    } else {
        int q = bx - 132;
        int zz = q >> 8;
        q &= 255;
        int by = q >> 4, bxx = q & 15;
        const float* S = zz ? Wo : Wk;
        float* D = zz ? g_WoT : g_WkT;
        float (*t)[33] = (float(*)[33]) & sm[0][0][0];
        int lx = tid & 31, ly = tid >> 5;
        int x = bxx * 32 + lx, y0 = by * 32;
#pragma unroll
        for (int r = ly; r < 32; r += 8) t[r][lx] = S[(long)(y0 + r) * 512 + x];
        __syncthreads();
        int xo = y0 + lx;
#pragma unroll
        for (int r = ly; r < 32; r += 8) D[(long)(bxx * 32 + r) * 512 + xo] = t[lx][r];
    }
}

// ==================== tf32 mma.sync GEMM core ====================
// C = A[1024x512] @ B^T (B K-major [512n][512k]) + bias. 64x64 CTA tile.
// mode 0: row-major C (ld 512). mode 1: scatter [z][n&63][t]. mode 2: [z][t][n&63].
__device__ __forceinline__ void gemm_core(
    const float* __restrict__ A, const float* __restrict__ B,
    const float* __restrict__ bias, float* __restrict__ C, int mode) {
    __shared__ uint32_t As[2][2048];
    __shared__ uint32_t Bs[2][2048];
    const int tid = threadIdx.x;
    const int wid = tid >> 5, lane = tid & 31;
    const int m0 = blockIdx.y * 64, n0 = blockIdx.x * 64;

    float4 apf[2], bpf[2];
    auto ldg = [&](int ch) {
        int k0 = ch << 5;
#pragma unroll
        for (int r = 0; r < 2; r++) {
            int j = tid + 256 * r;
            int row = j >> 3, c4 = (j & 7) << 2;
            apf[r] = *(const float4*)&A[(long)(m0 + row) * 512 + k0 + c4];
            bpf[r] = *(const float4*)&B[(long)(n0 + row) * 512 + k0 + c4];
        }
    };
    auto sts = [&](int buf) {
#pragma unroll
        for (int r = 0; r < 2; r++) {
            int j = tid + 256 * r;
            int row = j >> 3, c4 = (j & 7) << 2;
            int ks = c4 >> 3, chi = (c4 >> 2) & 1;
            {
                int mt = row >> 4, rlo = row & 15;
                int reg = (rlo >> 3) + (chi << 1);
                int off = (mt * 4 + ks) * 128 + (rlo & 7) * 16 + reg;
                As[buf][off + 0] = f2tf32(apf[r].x);
                As[buf][off + 4] = f2tf32(apf[r].y);
                As[buf][off + 8] = f2tf32(apf[r].z);
                As[buf][off + 12] = f2tf32(apf[r].w);
            }
            {
                int nt = row >> 3, g = row & 7;
                int off = (nt * 4 + ks) * 64 + g * 8 + chi;
                Bs[buf][off + 0] = f2tf32(bpf[r].x);
                Bs[buf][off + 2] = f2tf32(bpf[r].y);
                Bs[buf][off + 4] = f2tf32(bpf[r].z);
                Bs[buf][off + 6] = f2tf32(bpf[r].w);
            }
        }
    };

    const int wm = wid >> 2, wn = wid & 3;
    float acc[2][2][4] = {};
    auto compute = [&](int buf) {
#pragma unroll
        for (int ks = 0; ks < 4; ks++) {
            uint32_t a[2][4], b[2][2];
#pragma unroll
            for (int i = 0; i < 2; i++) {
                int mt = wm * 2 + i;
                uint4 v = *(const uint4*)&As[buf][(mt * 4 + ks) * 128 + lane * 4];
                a[i][0] = v.x; a[i][1] = v.y; a[i][2] = v.z; a[i][3] = v.w;
            }
#pragma unroll
            for (int j = 0; j < 2; j++) {
                int nt = wn * 2 + j;
                uint2 v = *(const uint2*)&Bs[buf][(nt * 4 + ks) * 64 + lane * 2];
                b[j][0] = v.x; b[j][1] = v.y;
            }
#pragma unroll
            for (int i = 0; i < 2; i++)
#pragma unroll
                for (int j = 0; j < 2; j++) mma_m16n8k8(acc[i][j], a[i], b[j]);
        }
    };

    ldg(0);
    sts(0);
    __syncthreads();
    for (int ch = 0; ch < 16; ch++) {
        if (ch + 1 < 16) ldg(ch + 1);
        compute(ch & 1);
        if (ch + 1 < 16) sts((ch + 1) & 1);
        __syncthreads();
    }

    const int g = lane >> 2, t4 = lane & 3;
#pragma unroll
    for (int i = 0; i < 2; i++)
#pragma unroll
        for (int j = 0; j < 2; j++) {
            int m = m0 + wm * 32 + i * 16 + g;
            int n = n0 + wn * 16 + j * 8 + t4 * 2;
            float c0 = acc[i][j][0], c1 = acc[i][j][1];
            float c2 = acc[i][j][2], c3 = acc[i][j][3];
            if (bias) {
                float b0 = bias[n], b1 = bias[n + 1];
                c0 += b0; c1 += b1; c2 += b0; c3 += b1;
            }
            if (mode == 0) {
                *(float2*)&C[(long)m * 512 + n] = make_float2(c0, c1);
                *(float2*)&C[(long)(m + 8) * 512 + n] = make_float2(c2, c3);
            } else if (mode == 1) {
                int bb = m >> 9, t = m & 511;
                long base0 = ((long)((bb << 3) + (n >> 6)) * 64 + (n & 63)) * 512;
                C[base0 + t] = c0;
                C[base0 + 512 + t] = c1;
                C[base0 + t + 8] = c2;
                C[base0 + 512 + t + 8] = c3;
            } else {
                int bb = m >> 9, t = m & 511;
                long r0 = ((long)((bb << 3) + (n >> 6)) * 512 + t) * 64 + (n & 63);
                *(float2*)&C[r0] = make_float2(c0, c1);
                *(float2*)&C[r0 + 8 * 64] = make_float2(c2, c3);
            }
        }
}

// three projections in one launch (z = task)
__global__ void __launch_bounds__(256) proj_mma(
    const float* __restrict__ query, const float* __restrict__ key,
    const float* __restrict__ bk) {
    int task = blockIdx.z;
    if (task == 0)      gemm_core(query, g_WqEffT, g_biasQ, g_qhE, 1);
    else if (task == 1) gemm_core(key, g_WkEffT, g_biasK, g_khbE, 1);
    else                gemm_core(key, g_WkT, bk, g_KpR, 2);
}
__global__ void __launch_bounds__(256) outg_mma(
    const float* __restrict__ bo, float* __restrict__ out) {
    gemm_core(g_merged, g_WoT, bo, out, 0);
}

// ==================== fused score + online-softmax + AV ====================
// grid (16 t-tiles, 16 z). Per CTA: rows t0..t0+31 of one (b,h).
__global__ void __launch_bounds__(256) fused_attn(const float* __restrict__ va) {
    const int t0 = blockIdx.x * 32;
    const int z = blockIdx.y;
    const int b = z >> 3, h = z & 7;
    __shared__ float qse[64][36];   // [e][t]
    __shared__ float kse[64][68];   // [e][s]; rows 0..31 reused as p[t][s]
    __shared__ float kp[64][68];    // [s][d]
    __shared__ float vsh[64];
    const int tid = threadIdx.x;
    const float* qbase = g_qhE + (long)z * 32768;
    const float* kbase = g_khbE + (long)z * 32768;
    const float* kpbase = g_KpR + (long)z * 32768;

#pragma unroll
    for (int r = 0; r < 2; r++) {
        int idx = tid + r * 256;
        int row = idx >> 3, c4 = (idx & 7) << 2;
        *(float4*)&qse[row][c4] = *(const float4*)&qbase[(long)row * 512 + t0 + c4];
    }
    if (tid < 64) vsh[tid] = va[h * 64 + tid];

    const int tm = (tid >> 4) * 2, tn = (tid & 15) * 4;
    float out[2][4] = {};
    float mrow[2] = {-1e30f, -1e30f};
    float lrow[2] = {0.f, 0.f};
    float* pbuf = &kse[0][0];

    for (int c = 0; c < 8; c++) {
        const int s0 = c * 64;
        __syncthreads();  // prior chunk consumers done with kse/kp
#pragma unroll
        for (int r = 0; r < 4; r++) {
            int idx = tid + r * 256;
            int row = idx >> 4, c4 = (idx & 15) << 2;
            *(float4*)&kse[row][c4] = *(const float4*)&kbase[(long)row * 512 + s0 + c4];
            *(float4*)&kp[row][c4] = *(const float4*)&kpbase[(long)(s0 + row) * 64 + c4];
        }
        __syncthreads();

        float sc[2][4] = {};
#pragma unroll 8
        for (int e = 0; e < 64; e++) {
            float vv = vsh[e];
            float2 q2 = *(const float2*)&qse[e][tm];
            float4 kv = *(const float4*)&kse[e][tn];
            sc[0][0] += vv * tanh_fast(q2.x + kv.x);
            sc[0][1] += vv * tanh_fast(q2.x + kv.y);
            sc[0][2] += vv * tanh_fast(q2.x + kv.z);
            sc[0][3] += vv * tanh_fast(q2.x + kv.w);
            sc[1][0] += vv * tanh_fast(q2.y + kv.x);
            sc[1][1] += vv * tanh_fast(q2.y + kv.y);
            sc[1][2] += vv * tanh_fast(q2.y + kv.z);
            sc[1][3] += vv * tanh_fast(q2.y + kv.w);
        }

        float rm[2], rs[2], alpha[2];
#pragma unroll
        for (int i = 0; i < 2; i++)
            rm[i] = fmaxf(fmaxf(sc[i][0], sc[i][1]), fmaxf(sc[i][2], sc[i][3]));
#pragma unroll
        for (int o = 8; o; o >>= 1) {
            rm[0] = fmaxf(rm[0], __shfl_xor_sync(0xffffffffu, rm[0], o));
            rm[1] = fmaxf(rm[1], __shfl_xor_sync(0xffffffffu, rm[1], o));
        }
#pragma unroll
        for (int i = 0; i < 2; i++) {
            float mn = fmaxf(mrow[i], rm[i]);
            alpha[i] = __expf(mrow[i] - mn);
            mrow[i] = mn;
#pragma unroll
            for (int j = 0; j < 4; j++) sc[i][j] = __expf(sc[i][j] - mn);
            rs[i] = (sc[i][0] + sc[i][1]) + (sc[i][2] + sc[i][3]);
        }
#pragma unroll
        for (int o = 8; o; o >>= 1) {
            rs[0] += __shfl_xor_sync(0xffffffffu, rs[0], o);
            rs[1] += __shfl_xor_sync(0xffffffffu, rs[1], o);
        }
#pragma unroll
        for (int i = 0; i < 2; i++) {
            lrow[i] = lrow[i] * alpha[i] + rs[i];
#pragma unroll
            for (int j = 0; j < 4; j++) out[i][j] *= alpha[i];
        }
        __syncthreads();  // all kse reads finished
        *(float4*)&pbuf[tm * 68 + tn] = make_float4(sc[0][0], sc[0][1], sc[0][2], sc[0][3]);
        *(float4*)&pbuf[(tm + 1) * 68 + tn] = make_float4(sc[1][0], sc[1][1], sc[1][2], sc[1][3]);
        __syncthreads();

#pragma unroll 4
        for (int s = 0; s < 64; s++) {
            float p0 = pbuf[tm * 68 + s];
            float p1 = pbuf[(tm + 1) * 68 + s];
            float4 kv = *(const float4*)&kp[s][tn];
            out[0][0] += p0 * kv.x; out[0][1] += p0 * kv.y;
            out[0][2] += p0 * kv.z; out[0][3] += p0 * kv.w;
            out[1][0] += p1 * kv.x; out[1][1] += p1 * kv.y;
            out[1][2] += p1 * kv.z; out[1][3] += p1 * kv.w;
        }
    }

    float inv0 = __fdividef(1.f, lrow[0]);
    float inv1 = __fdividef(1.f, lrow[1]);
    long r0 = (long)(b * 512 + t0 + tm) * 512 + h * 64 + tn;
    *(float4*)&g_merged[r0] =
        make_float4(out[0][0] * inv0, out[0][1] * inv0, out[0][2] * inv0, out[0][3] * inv0);
    *(float4*)&g_merged[r0 + 512] =
        make_float4(out[1][0] * inv1, out[1][1] * inv1, out[1][2] * inv1, out[1][3] * inv1);
}

// ---------------- launcher ----------------
extern "C" void kernel_launch(void* const* d_in, const int* in_sizes, int n_in,
                              void* d_out, int out_size) {
    const float* query = (const float*)d_in[0];
    const float* key   = (const float*)d_in[1];
    const float* Wq   = (const float*)d_in[3];
    const float* bq   = (const float*)d_in[4];
    const float* Wk   = (const float*)d_in[5];
    const float* bk   = (const float*)d_in[6];
    const float* Wq_h = (const float*)d_in[9];
    const float* Wk_h = (const float*)d_in[10];
    const float* va_h = (const float*)d_in[11];
    const float* b_h  = (const float*)d_in[12];
    const float* Wo   = (const float*)d_in[13];
    const float* bo   = (const float*)d_in[14];
    float* out = (float*)d_out;

    prep_all<<<644, 256>>>(bq, Wq_h, bk, Wk_h, b_h, Wq, Wk, Wo);
    proj_mma<<<dim3(8, 16, 3), 256>>>(query, key, bk);
    fused_attn<<<dim3(16, 16), 256>>>(va_h);
    outg_mma<<<dim3(8, 16), 256>>>(bo, out);
}